// round 1
// baseline (speedup 1.0000x reference)
#include <cuda_runtime.h>
#include <cuda_bf16.h>

// Problem constants (match reference_code)
#define N_NODES   20000
#define N_EDGES   320000
#define N_GRAPHS  64
#define NODE_DIM  128
#define GLOB_DIM  16
#define HIDDEN    256
#define NUM_LAYERS 4

// ---------------------------------------------------------------------------
// Scratch (static __device__ allocations — no cudaMalloc anywhere)
// ---------------------------------------------------------------------------
__device__ float g_hA[N_NODES * HIDDEN];
__device__ float g_hB[N_NODES * HIDDEN];
__device__ float g_z [N_NODES * HIDDEN];
__device__ float g_t [N_NODES * HIDDEN];

__device__ int   g_deg   [N_NODES];
__device__ int   g_rowptr[N_NODES + 1];
__device__ int   g_cursor[N_NODES];
__device__ int   g_col   [N_EDGES];

__device__ float g_pooled[N_GRAPHS * HIDDEN];
__device__ float g_cnt   [N_GRAPHS];

// ---------------------------------------------------------------------------
// CSR build
// ---------------------------------------------------------------------------
__global__ void k_zero() {
    int i = blockIdx.x * blockDim.x + threadIdx.x;
    if (i < N_NODES) g_deg[i] = 0;
    if (i < N_GRAPHS * HIDDEN) g_pooled[i] = 0.f;
    if (i < N_GRAPHS) g_cnt[i] = 0.f;
}

__global__ void k_count(const int* __restrict__ dst) {
    int e = blockIdx.x * blockDim.x + threadIdx.x;
    if (e < N_EDGES) atomicAdd(&g_deg[dst[e]], 1);
}

// Single-block exclusive scan over g_deg -> g_rowptr (+ cursor copy)
__global__ void k_scan() {
    const int T = 512;
    const int CH = (N_NODES + T - 1) / T;   // 40
    __shared__ int part[T];
    int t = threadIdx.x;
    int base = t * CH;
    int s = 0;
    for (int j = 0; j < CH; j++) {
        int i = base + j;
        if (i < N_NODES) s += g_deg[i];
    }
    part[t] = s;
    __syncthreads();
    // Kogge-Stone inclusive scan of partials
    for (int off = 1; off < T; off <<= 1) {
        int v = (t >= off) ? part[t - off] : 0;
        __syncthreads();
        part[t] += v;
        __syncthreads();
    }
    int run = (t > 0) ? part[t - 1] : 0;
    for (int j = 0; j < CH; j++) {
        int i = base + j;
        if (i < N_NODES) {
            g_rowptr[i] = run;
            g_cursor[i] = run;
            run += g_deg[i];
        }
    }
    if (t == T - 1) g_rowptr[N_NODES] = run;
}

__global__ void k_fill(const int* __restrict__ src, const int* __restrict__ dst) {
    int e = blockIdx.x * blockDim.x + threadIdx.x;
    if (e < N_EDGES) {
        int d = dst[e];
        int p = atomicAdd(&g_cursor[d], 1);
        g_col[p] = src[e];
    }
}

// ---------------------------------------------------------------------------
// GIN aggregation (gather form, atomic-free):
//   z[v] = (1+eps[l]) * h[v] + sum_{s in N_in(v)} h[s]
// DIM4 = feature_dim / 4 (float4 lanes per node). blockDim = 128.
// ---------------------------------------------------------------------------
template <int DIM4>
__global__ void k_aggr(const float* __restrict__ h, float* __restrict__ z,
                       const float* __restrict__ eps, int layer) {
    const int NPB = 128 / DIM4;
    int v = blockIdx.x * NPB + threadIdx.x / DIM4;
    if (v >= N_NODES) return;
    int t = threadIdx.x % DIM4;
    float ep = 1.0f + eps[layer];
    const float4* h4 = (const float4*)h;
    float4 a = h4[(size_t)v * DIM4 + t];
    float4 acc;
    acc.x = ep * a.x; acc.y = ep * a.y; acc.z = ep * a.z; acc.w = ep * a.w;
    int s0 = g_rowptr[v], s1 = g_rowptr[v + 1];
    for (int j = s0; j < s1; ++j) {
        int s = g_col[j];
        float4 b = h4[(size_t)s * DIM4 + t];
        acc.x += b.x; acc.y += b.y; acc.z += b.z; acc.w += b.w;
    }
    ((float4*)z)[(size_t)v * DIM4 + t] = acc;
}

// ---------------------------------------------------------------------------
// SGEMM: C[n x 256] = epilogue(A[n x K] @ B[K x 256] + bias)
// epilogue: ReLU, then optional residual add (RESID).
// 128x128 tile, BK=16, 256 threads, 8x8 micro-tile.
// ---------------------------------------------------------------------------
template <bool RESID>
__global__ __launch_bounds__(256, 2)
void k_gemm(const float* __restrict__ A, const float* __restrict__ B,
            const float* __restrict__ bias, const float* __restrict__ R,
            float* __restrict__ C, int n, int K) {
    __shared__ float As[16][128 + 4];
    __shared__ float Bs[16][128];
    int row0 = blockIdx.y * 128;
    int col0 = blockIdx.x * 128;
    int tid = threadIdx.x;
    int tx = tid & 15;       // 0..15 -> 8 output cols each
    int ty = tid >> 4;       // 0..15 -> 8 output rows each
    float acc[8][8];
#pragma unroll
    for (int i = 0; i < 8; i++)
#pragma unroll
        for (int j = 0; j < 8; j++) acc[i][j] = 0.f;

    for (int k0 = 0; k0 < K; k0 += 16) {
#pragma unroll
        for (int i = 0; i < 2; i++) {
            int idx = tid + i * 256;
            // A tile: 128 rows x 16 cols (store transposed)
            int ar = idx >> 2;
            int ac = (idx & 3) * 4;
            int gr = row0 + ar;
            float4 av = make_float4(0.f, 0.f, 0.f, 0.f);
            if (gr < n) av = *(const float4*)&A[(size_t)gr * K + k0 + ac];
            As[ac + 0][ar] = av.x;
            As[ac + 1][ar] = av.y;
            As[ac + 2][ar] = av.z;
            As[ac + 3][ar] = av.w;
            // B tile: 16 rows x 128 cols
            int br = idx >> 5;
            int bc = (idx & 31) * 4;
            float4 bv = *(const float4*)&B[(size_t)(k0 + br) * 256 + col0 + bc];
            *(float4*)&Bs[br][bc] = bv;
        }
        __syncthreads();
#pragma unroll
        for (int k = 0; k < 16; k++) {
            float ra[8], rb[8];
#pragma unroll
            for (int i = 0; i < 8; i++) ra[i] = As[k][ty * 8 + i];
#pragma unroll
            for (int j = 0; j < 8; j++) rb[j] = Bs[k][tx * 8 + j];
#pragma unroll
            for (int i = 0; i < 8; i++)
#pragma unroll
                for (int j = 0; j < 8; j++) acc[i][j] += ra[i] * rb[j];
        }
        __syncthreads();
    }
    // epilogue
#pragma unroll
    for (int i = 0; i < 8; i++) {
        int r = row0 + ty * 8 + i;
        if (r >= n) continue;
#pragma unroll
        for (int j = 0; j < 8; j++) {
            int c = col0 + tx * 8 + j;
            float v = acc[i][j] + bias[c];
            v = fmaxf(v, 0.f);
            if (RESID) v += R[(size_t)r * 256 + c];
            C[(size_t)r * 256 + c] = v;
        }
    }
}

// ---------------------------------------------------------------------------
// Pooling: batch is sorted -> run-length accumulate, one atomic per segment.
// blockDim = 256 (one dim per thread), each block covers 128 nodes.
// ---------------------------------------------------------------------------
__global__ void k_pool(const float* __restrict__ h, const int* __restrict__ batch) {
    __shared__ int sb[128];
    int i0 = blockIdx.x * 128;
    int d = threadIdx.x;
    int end = N_NODES - i0;
    if (end > 128) end = 128;
    if (d < 128 && d < end) sb[d] = batch[i0 + d];
    __syncthreads();
    int cur = sb[0];
    float acc = 0.f;
    for (int t = 0; t < end; t++) {
        int b = sb[t];
        if (b != cur) {
            atomicAdd(&g_pooled[cur * HIDDEN + d], acc);
            acc = 0.f;
            cur = b;
        }
        acc += h[(size_t)(i0 + t) * HIDDEN + d];
    }
    atomicAdd(&g_pooled[cur * HIDDEN + d], acc);
    if (d == 0) {
        int c = 0, cb = sb[0];
        for (int t = 0; t < end; t++) {
            if (sb[t] != cb) {
                atomicAdd(&g_cnt[cb], (float)c);
                c = 0;
                cb = sb[t];
            }
            c++;
        }
        atomicAdd(&g_cnt[cb], (float)c);
    }
}

// ---------------------------------------------------------------------------
// Head: feat = [pooled/count, g]; out = relu(feat@hW1+hb1) @ hW2 + hb2
// one block per graph, 256 threads (one hidden unit per thread)
// ---------------------------------------------------------------------------
__global__ void k_head(const float* __restrict__ g,
                       const float* __restrict__ hW1, const float* __restrict__ hb1,
                       const float* __restrict__ hW2, const float* __restrict__ hb2,
                       float* __restrict__ out) {
    __shared__ float feat[HIDDEN + GLOB_DIM];
    __shared__ float red[256];
    int gi = blockIdx.x;
    int t = threadIdx.x;
    float cnt = fmaxf(g_cnt[gi], 1.0f);
    feat[t] = g_pooled[gi * HIDDEN + t] / cnt;
    if (t < GLOB_DIM) feat[HIDDEN + t] = g[gi * GLOB_DIM + t];
    __syncthreads();
    float acc = hb1[t];
    for (int k = 0; k < HIDDEN + GLOB_DIM; k++)
        acc += feat[k] * hW1[k * HIDDEN + t];
    acc = fmaxf(acc, 0.f) * hW2[t];
    red[t] = acc;
    __syncthreads();
    for (int off = 128; off > 0; off >>= 1) {
        if (t < off) red[t] += red[t + off];
        __syncthreads();
    }
    if (t == 0) out[gi] = red[0] + hb2[0];
}

// ---------------------------------------------------------------------------
// kernel_launch
// ---------------------------------------------------------------------------
extern "C" void kernel_launch(void* const* d_in, const int* in_sizes, int n_in,
                              void* d_out, int out_size) {
    const float* x     = (const float*)d_in[0];
    const int*   ei    = (const int*)  d_in[1];
    const int*   batch = (const int*)  d_in[2];
    const float* g     = (const float*)d_in[3];
    const float* W1[NUM_LAYERS], *b1[NUM_LAYERS], *W2[NUM_LAYERS], *b2[NUM_LAYERS];
    for (int l = 0; l < NUM_LAYERS; l++) {
        W1[l] = (const float*)d_in[4 + 4 * l + 0];
        b1[l] = (const float*)d_in[4 + 4 * l + 1];
        W2[l] = (const float*)d_in[4 + 4 * l + 2];
        b2[l] = (const float*)d_in[4 + 4 * l + 3];
    }
    const float* eps = (const float*)d_in[20];
    const float* hW1 = (const float*)d_in[21];
    const float* hb1 = (const float*)d_in[22];
    const float* hW2 = (const float*)d_in[23];
    const float* hb2 = (const float*)d_in[24];
    float* out = (float*)d_out;

    const int* src = ei;            // edge_index[0]
    const int* dst = ei + N_EDGES;  // edge_index[1]

    float *hA, *hB, *z, *t;
    cudaGetSymbolAddress((void**)&hA, g_hA);
    cudaGetSymbolAddress((void**)&hB, g_hB);
    cudaGetSymbolAddress((void**)&z,  g_z);
    cudaGetSymbolAddress((void**)&t,  g_t);

    // CSR build (once per launch; reused by all 4 layers)
    k_zero <<<(N_NODES + 255) / 256, 256>>>();
    k_count<<<(N_EDGES + 255) / 256, 256>>>(dst);
    k_scan <<<1, 512>>>();
    k_fill <<<(N_EDGES + 255) / 256, 256>>>(src, dst);

    dim3 ggrid(2, (N_NODES + 127) / 128);   // 256 output cols / 128, row tiles

    const float* h_in = x;
    float* h_out = hA;
    for (int l = 0; l < NUM_LAYERS; l++) {
        int din = (l == 0) ? NODE_DIM : HIDDEN;
        if (din == NODE_DIM)
            k_aggr<NODE_DIM / 4><<<(N_NODES + 3) / 4, 128>>>(h_in, z, eps, l);
        else
            k_aggr<HIDDEN / 4><<<(N_NODES + 1) / 2, 128>>>(h_in, z, eps, l);
        // t = relu(z @ W1 + b1)
        k_gemm<false><<<ggrid, 256>>>(z, W1[l], b1[l], nullptr, t, N_NODES, din);
        // h_out = relu(t @ W2 + b2) [+ h_in if residual shapes match]
        if (l == 0)
            k_gemm<false><<<ggrid, 256>>>(t, W2[l], b2[l], nullptr, h_out, N_NODES, HIDDEN);
        else
            k_gemm<true><<<ggrid, 256>>>(t, W2[l], b2[l], h_in, h_out, N_NODES, HIDDEN);
        h_in = h_out;
        h_out = (h_out == hA) ? hB : hA;
    }

    // h_in now points at the final node features
    k_pool<<<(N_NODES + 127) / 128, 256>>>(h_in, batch);
    k_head<<<N_GRAPHS, 256>>>(g, hW1, hb1, hW2, hb2, out);
}

// round 3
// speedup vs baseline: 1.0107x; 1.0107x over previous
#include <cuda_runtime.h>
#include <cstdint>
#include <cstddef>

// Problem constants
#define N_NODES   20000
#define N_EDGES   320000
#define N_GRAPHS  64
#define NODE_DIM  128
#define GLOB_DIM  16
#define HIDDEN    256
#define NUM_LAYERS 4

// ---------------------------------------------------------------------------
// Scratch (static __device__ allocations)
// ---------------------------------------------------------------------------
__device__ float g_hA[N_NODES * HIDDEN];
__device__ float g_hB[N_NODES * HIDDEN];
__device__ float g_z [N_NODES * HIDDEN];
__device__ float g_t [N_NODES * HIDDEN];

__device__ int   g_deg   [N_NODES];
__device__ int   g_rowptr[N_NODES + 1];
__device__ int   g_cursor[N_NODES];
__device__ int   g_col   [N_EDGES];

__device__ float g_pooled[N_GRAPHS * HIDDEN];
__device__ float g_cnt   [N_GRAPHS];

// ---------------------------------------------------------------------------
// CSR build
// ---------------------------------------------------------------------------
__global__ void k_zero() {
    int i = blockIdx.x * blockDim.x + threadIdx.x;
    if (i < N_NODES) g_deg[i] = 0;
    if (i < N_GRAPHS * HIDDEN) g_pooled[i] = 0.f;
    if (i < N_GRAPHS) g_cnt[i] = 0.f;
}

__global__ void k_count(const int* __restrict__ dst) {
    int e = blockIdx.x * blockDim.x + threadIdx.x;
    if (e < N_EDGES) atomicAdd(&g_deg[dst[e]], 1);
}

__global__ void k_scan() {
    const int T = 512;
    const int CH = (N_NODES + T - 1) / T;
    __shared__ int part[T];
    int t = threadIdx.x;
    int base = t * CH;
    int s = 0;
    for (int j = 0; j < CH; j++) {
        int i = base + j;
        if (i < N_NODES) s += g_deg[i];
    }
    part[t] = s;
    __syncthreads();
    for (int off = 1; off < T; off <<= 1) {
        int v = (t >= off) ? part[t - off] : 0;
        __syncthreads();
        part[t] += v;
        __syncthreads();
    }
    int run = (t > 0) ? part[t - 1] : 0;
    for (int j = 0; j < CH; j++) {
        int i = base + j;
        if (i < N_NODES) {
            g_rowptr[i] = run;
            g_cursor[i] = run;
            run += g_deg[i];
        }
    }
    if (t == T - 1) g_rowptr[N_NODES] = run;
}

__global__ void k_fill(const int* __restrict__ src, const int* __restrict__ dst) {
    int e = blockIdx.x * blockDim.x + threadIdx.x;
    if (e < N_EDGES) {
        int d = dst[e];
        int p = atomicAdd(&g_cursor[d], 1);
        g_col[p] = src[e];
    }
}

// ---------------------------------------------------------------------------
// GIN aggregation (gather, atomic-free)
// ---------------------------------------------------------------------------
template <int DIM4>
__global__ void k_aggr(const float* __restrict__ h, float* __restrict__ z,
                       const float* __restrict__ eps, int layer) {
    const int NPB = 128 / DIM4;
    int v = blockIdx.x * NPB + threadIdx.x / DIM4;
    if (v >= N_NODES) return;
    int t = threadIdx.x % DIM4;
    float ep = 1.0f + eps[layer];
    const float4* h4 = (const float4*)h;
    float4 a = h4[(size_t)v * DIM4 + t];
    float4 acc;
    acc.x = ep * a.x; acc.y = ep * a.y; acc.z = ep * a.z; acc.w = ep * a.w;
    int s0 = g_rowptr[v], s1 = g_rowptr[v + 1];
    for (int j = s0; j < s1; ++j) {
        int s = g_col[j];
        float4 b = h4[(size_t)s * DIM4 + t];
        acc.x += b.x; acc.y += b.y; acc.z += b.z; acc.w += b.w;
    }
    ((float4*)z)[(size_t)v * DIM4 + t] = acc;
}

// ---------------------------------------------------------------------------
// Tensor-core GEMM (mma.sync tf32, 3xTF32 split for fp32-level accuracy)
// C[n x 256] = epi(A[n x K] @ B[K x 256] + bias), optional residual
// Block: 256 threads (8 warps, 2x4), tile 128x128, BK=16. Warp tile 64x32.
// ---------------------------------------------------------------------------
__device__ __forceinline__ void split_tf32(float x, uint32_t& hi, uint32_t& lo) {
    uint32_t h;
    asm("cvt.rna.tf32.f32 %0, %1;" : "=r"(h) : "f"(x));
    float lf = x - __uint_as_float(h);
    uint32_t l;
    asm("cvt.rna.tf32.f32 %0, %1;" : "=r"(l) : "f"(lf));
    hi = h; lo = l;
}

__device__ __forceinline__ void mma8(float* c, const uint32_t* a, const uint32_t* b) {
    asm volatile(
        "mma.sync.aligned.m16n8k8.row.col.f32.tf32.tf32.f32 "
        "{%0,%1,%2,%3}, {%4,%5,%6,%7}, {%8,%9}, {%0,%1,%2,%3};"
        : "+f"(c[0]), "+f"(c[1]), "+f"(c[2]), "+f"(c[3])
        : "r"(a[0]), "r"(a[1]), "r"(a[2]), "r"(a[3]), "r"(b[0]), "r"(b[1]));
}

template <bool RESID>
__global__ __launch_bounds__(256, 1)
void k_gemm(const float* __restrict__ A, const float* __restrict__ B,
            const float* __restrict__ bias, const float* __restrict__ R,
            float* __restrict__ C, int n, int K) {
    __shared__ float As[16][136];   // A^T tile: As[k][m]
    __shared__ float Bs[16][136];   // B tile:   Bs[k][nn]
    int row0 = blockIdx.y * 128;
    int col0 = blockIdx.x * 128;
    int tid  = threadIdx.x;
    int w    = tid >> 5;
    int lane = tid & 31;
    int qid  = lane >> 2;   // 0..7
    int tq   = lane & 3;    // 0..3
    int m0w  = (w >> 2) * 64;   // warp row offset within tile
    int n0w  = (w & 3) * 32;    // warp col offset within tile

    float acc[4][4][4];
#pragma unroll
    for (int i = 0; i < 4; i++)
#pragma unroll
        for (int j = 0; j < 4; j++)
#pragma unroll
            for (int q = 0; q < 4; q++) acc[i][j][q] = 0.f;

    for (int k0 = 0; k0 < K; k0 += 16) {
        // ---- load tiles (same scheme as proven fp32 version) ----
#pragma unroll
        for (int i = 0; i < 2; i++) {
            int idx = tid + i * 256;
            int ar = idx >> 2;
            int ac = (idx & 3) * 4;
            int gr = row0 + ar;
            float4 av = make_float4(0.f, 0.f, 0.f, 0.f);
            if (gr < n) av = *(const float4*)&A[(size_t)gr * K + k0 + ac];
            As[ac + 0][ar] = av.x;
            As[ac + 1][ar] = av.y;
            As[ac + 2][ar] = av.z;
            As[ac + 3][ar] = av.w;
            int br = idx >> 5;
            int bc = (idx & 31) * 4;
            float4 bv = *(const float4*)&B[(size_t)(k0 + br) * 256 + col0 + bc];
            *(float4*)&Bs[br][bc] = bv;
        }
        __syncthreads();

        // ---- tensor-core compute ----
#pragma unroll
        for (int kk = 0; kk < 16; kk += 8) {
            uint32_t ah[4][4], al[4][4];
#pragma unroll
            for (int mb = 0; mb < 4; mb++) {
                int r0 = m0w + mb * 16 + qid;
                float x0 = As[kk + tq][r0];
                float x1 = As[kk + tq][r0 + 8];
                float x2 = As[kk + tq + 4][r0];
                float x3 = As[kk + tq + 4][r0 + 8];
                split_tf32(x0, ah[mb][0], al[mb][0]);
                split_tf32(x1, ah[mb][1], al[mb][1]);
                split_tf32(x2, ah[mb][2], al[mb][2]);
                split_tf32(x3, ah[mb][3], al[mb][3]);
            }
            uint32_t bh[4][2], bl[4][2];
#pragma unroll
            for (int nb = 0; nb < 4; nb++) {
                int c = n0w + nb * 8 + qid;
                float y0 = Bs[kk + tq][c];
                float y1 = Bs[kk + tq + 4][c];
                split_tf32(y0, bh[nb][0], bl[nb][0]);
                split_tf32(y1, bh[nb][1], bl[nb][1]);
            }
#pragma unroll
            for (int mb = 0; mb < 4; mb++)
#pragma unroll
                for (int nb = 0; nb < 4; nb++) {
                    mma8(acc[mb][nb], al[mb], bh[nb]);
                    mma8(acc[mb][nb], ah[mb], bl[nb]);
                    mma8(acc[mb][nb], ah[mb], bh[nb]);
                }
        }
        __syncthreads();
    }

    // ---- epilogue: bias + ReLU (+ residual) ----
#pragma unroll
    for (int mb = 0; mb < 4; mb++) {
        int r0g = row0 + m0w + mb * 16 + qid;
        int r1g = r0g + 8;
#pragma unroll
        for (int nb = 0; nb < 4; nb++) {
            int cg = col0 + n0w + nb * 8 + tq * 2;
            float bsum0 = bias[cg], bsum1 = bias[cg + 1];
            if (r0g < n) {
                float v0 = fmaxf(acc[mb][nb][0] + bsum0, 0.f);
                float v1 = fmaxf(acc[mb][nb][1] + bsum1, 0.f);
                if (RESID) {
                    v0 += R[(size_t)r0g * 256 + cg];
                    v1 += R[(size_t)r0g * 256 + cg + 1];
                }
                C[(size_t)r0g * 256 + cg]     = v0;
                C[(size_t)r0g * 256 + cg + 1] = v1;
            }
            if (r1g < n) {
                float v2 = fmaxf(acc[mb][nb][2] + bsum0, 0.f);
                float v3 = fmaxf(acc[mb][nb][3] + bsum1, 0.f);
                if (RESID) {
                    v2 += R[(size_t)r1g * 256 + cg];
                    v3 += R[(size_t)r1g * 256 + cg + 1];
                }
                C[(size_t)r1g * 256 + cg]     = v2;
                C[(size_t)r1g * 256 + cg + 1] = v3;
            }
        }
    }
}

// ---------------------------------------------------------------------------
// Pooling (sorted batch -> run-length accumulate)
// ---------------------------------------------------------------------------
__global__ void k_pool(const float* __restrict__ h, const int* __restrict__ batch) {
    __shared__ int sb[128];
    int i0 = blockIdx.x * 128;
    int d = threadIdx.x;
    int end = N_NODES - i0;
    if (end > 128) end = 128;
    if (d < 128 && d < end) sb[d] = batch[i0 + d];
    __syncthreads();
    int cur = sb[0];
    float acc = 0.f;
    for (int t = 0; t < end; t++) {
        int b = sb[t];
        if (b != cur) {
            atomicAdd(&g_pooled[cur * HIDDEN + d], acc);
            acc = 0.f;
            cur = b;
        }
        acc += h[(size_t)(i0 + t) * HIDDEN + d];
    }
    atomicAdd(&g_pooled[cur * HIDDEN + d], acc);
    if (d == 0) {
        int c = 0, cb = sb[0];
        for (int t = 0; t < end; t++) {
            if (sb[t] != cb) {
                atomicAdd(&g_cnt[cb], (float)c);
                c = 0;
                cb = sb[t];
            }
            c++;
        }
        atomicAdd(&g_cnt[cb], (float)c);
    }
}

// ---------------------------------------------------------------------------
// Head
// ---------------------------------------------------------------------------
__global__ void k_head(const float* __restrict__ g,
                       const float* __restrict__ hW1, const float* __restrict__ hb1,
                       const float* __restrict__ hW2, const float* __restrict__ hb2,
                       float* __restrict__ out) {
    __shared__ float feat[HIDDEN + GLOB_DIM];
    __shared__ float red[256];
    int gi = blockIdx.x;
    int t = threadIdx.x;
    float cnt = fmaxf(g_cnt[gi], 1.0f);
    feat[t] = g_pooled[gi * HIDDEN + t] / cnt;
    if (t < GLOB_DIM) feat[HIDDEN + t] = g[gi * GLOB_DIM + t];
    __syncthreads();
    float acc = hb1[t];
    for (int k = 0; k < HIDDEN + GLOB_DIM; k++)
        acc += feat[k] * hW1[k * HIDDEN + t];
    acc = fmaxf(acc, 0.f) * hW2[t];
    red[t] = acc;
    __syncthreads();
    for (int off = 128; off > 0; off >>= 1) {
        if (t < off) red[t] += red[t + off];
        __syncthreads();
    }
    if (t == 0) out[gi] = red[0] + hb2[0];
}

// ---------------------------------------------------------------------------
// kernel_launch
// ---------------------------------------------------------------------------
extern "C" void kernel_launch(void* const* d_in, const int* in_sizes, int n_in,
                              void* d_out, int out_size) {
    const float* x     = (const float*)d_in[0];
    const int*   ei    = (const int*)  d_in[1];
    const int*   batch = (const int*)  d_in[2];
    const float* g     = (const float*)d_in[3];
    const float* W1[NUM_LAYERS], *b1[NUM_LAYERS], *W2[NUM_LAYERS], *b2[NUM_LAYERS];
    for (int l = 0; l < NUM_LAYERS; l++) {
        W1[l] = (const float*)d_in[4 + 4 * l + 0];
        b1[l] = (const float*)d_in[4 + 4 * l + 1];
        W2[l] = (const float*)d_in[4 + 4 * l + 2];
        b2[l] = (const float*)d_in[4 + 4 * l + 3];
    }
    const float* eps = (const float*)d_in[20];
    const float* hW1 = (const float*)d_in[21];
    const float* hb1 = (const float*)d_in[22];
    const float* hW2 = (const float*)d_in[23];
    const float* hb2 = (const float*)d_in[24];
    float* out = (float*)d_out;

    const int* src = ei;
    const int* dst = ei + N_EDGES;

    float *hA, *hB, *z, *t;
    cudaGetSymbolAddress((void**)&hA, g_hA);
    cudaGetSymbolAddress((void**)&hB, g_hB);
    cudaGetSymbolAddress((void**)&z,  g_z);
    cudaGetSymbolAddress((void**)&t,  g_t);

    // CSR build
    k_zero <<<(N_NODES + 255) / 256, 256>>>();
    k_count<<<(N_EDGES + 255) / 256, 256>>>(dst);
    k_scan <<<1, 512>>>();
    k_fill <<<(N_EDGES + 255) / 256, 256>>>(src, dst);

    dim3 ggrid(2, (N_NODES + 127) / 128);

    const float* h_in = x;
    float* h_out = hA;
    for (int l = 0; l < NUM_LAYERS; l++) {
        int din = (l == 0) ? NODE_DIM : HIDDEN;
        if (din == NODE_DIM)
            k_aggr<NODE_DIM / 4><<<(N_NODES + 3) / 4, 128>>>(h_in, z, eps, l);
        else
            k_aggr<HIDDEN / 4><<<(N_NODES + 1) / 2, 128>>>(h_in, z, eps, l);
        k_gemm<false><<<ggrid, 256>>>(z, W1[l], b1[l], nullptr, t, N_NODES, din);
        if (l == 0)
            k_gemm<false><<<ggrid, 256>>>(t, W2[l], b2[l], nullptr, h_out, N_NODES, HIDDEN);
        else
            k_gemm<true ><<<ggrid, 256>>>(t, W2[l], b2[l], h_in, h_out, N_NODES, HIDDEN);
        h_in = h_out;
        h_out = (h_out == hA) ? hB : hA;
    }

    k_pool<<<(N_NODES + 127) / 128, 256>>>(h_in, batch);
    k_head<<<N_GRAPHS, 256>>>(g, hW1, hb1, hW2, hb2, out);
}

// round 4
// speedup vs baseline: 2.0273x; 2.0059x over previous
#include <cuda_runtime.h>
#include <cstdint>
#include <cstddef>

// Problem constants
#define N_NODES   20000
#define N_EDGES   320000
#define N_GRAPHS  64
#define NODE_DIM  128
#define GLOB_DIM  16
#define HIDDEN    256
#define NUM_LAYERS 4

// ---------------------------------------------------------------------------
// Scratch (static __device__ allocations)
// ---------------------------------------------------------------------------
__device__ float g_hA[N_NODES * HIDDEN];
__device__ float g_hB[N_NODES * HIDDEN];
__device__ float g_z [N_NODES * HIDDEN];
__device__ float g_t [N_NODES * HIDDEN];
__device__ float g_Wr[NUM_LAYERS * 2][HIDDEN * HIDDEN];  // tf32-rounded weights

__device__ int   g_deg   [N_NODES];
__device__ int   g_rowptr[N_NODES + 1];
__device__ int   g_cursor[N_NODES];
__device__ int   g_col   [N_EDGES];

__device__ float g_pooled[N_GRAPHS * HIDDEN];
__device__ float g_cnt   [N_GRAPHS];

// ---------------------------------------------------------------------------
// Helpers
// ---------------------------------------------------------------------------
__device__ __forceinline__ float rtf32(float x) {
    uint32_t r;
    asm("cvt.rna.tf32.f32 %0, %1;" : "=r"(r) : "f"(x));
    return __uint_as_float(r);
}

__device__ __forceinline__ void mma8(float* c, const uint32_t* a, const uint32_t* b) {
    asm volatile(
        "mma.sync.aligned.m16n8k8.row.col.f32.tf32.tf32.f32 "
        "{%0,%1,%2,%3}, {%4,%5,%6,%7}, {%8,%9}, {%0,%1,%2,%3};"
        : "+f"(c[0]), "+f"(c[1]), "+f"(c[2]), "+f"(c[3])
        : "r"(a[0]), "r"(a[1]), "r"(a[2]), "r"(a[3]), "r"(b[0]), "r"(b[1]));
}

__device__ __forceinline__ void cp16p(void* dst, const void* src, int srcbytes) {
    uint32_t d = (uint32_t)__cvta_generic_to_shared(dst);
    asm volatile("cp.async.cg.shared.global [%0], [%1], 16, %2;"
                 :: "r"(d), "l"(src), "r"(srcbytes));
}
__device__ __forceinline__ void cp16(void* dst, const void* src) {
    uint32_t d = (uint32_t)__cvta_generic_to_shared(dst);
    asm volatile("cp.async.cg.shared.global [%0], [%1], 16;"
                 :: "r"(d), "l"(src));
}
#define CP_COMMIT() asm volatile("cp.async.commit_group;" ::: "memory")

// ---------------------------------------------------------------------------
// CSR build
// ---------------------------------------------------------------------------
__global__ void k_zero() {
    int i = blockIdx.x * blockDim.x + threadIdx.x;
    if (i < N_NODES) g_deg[i] = 0;
    if (i < N_GRAPHS * HIDDEN) g_pooled[i] = 0.f;
    if (i < N_GRAPHS) g_cnt[i] = 0.f;
}

__global__ void k_count(const int* __restrict__ dst) {
    int e = blockIdx.x * blockDim.x + threadIdx.x;
    if (e < N_EDGES) atomicAdd(&g_deg[dst[e]], 1);
}

__global__ void k_scan() {
    const int T = 512;
    const int CH = (N_NODES + T - 1) / T;
    __shared__ int part[T];
    int t = threadIdx.x;
    int base = t * CH;
    int s = 0;
    for (int j = 0; j < CH; j++) {
        int i = base + j;
        if (i < N_NODES) s += g_deg[i];
    }
    part[t] = s;
    __syncthreads();
    for (int off = 1; off < T; off <<= 1) {
        int v = (t >= off) ? part[t - off] : 0;
        __syncthreads();
        part[t] += v;
        __syncthreads();
    }
    int run = (t > 0) ? part[t - 1] : 0;
    for (int j = 0; j < CH; j++) {
        int i = base + j;
        if (i < N_NODES) {
            g_rowptr[i] = run;
            g_cursor[i] = run;
            run += g_deg[i];
        }
    }
    if (t == T - 1) g_rowptr[N_NODES] = run;
}

__global__ void k_fill(const int* __restrict__ src, const int* __restrict__ dst) {
    int e = blockIdx.x * blockDim.x + threadIdx.x;
    if (e < N_EDGES) {
        int d = dst[e];
        int p = atomicAdd(&g_cursor[d], 1);
        g_col[p] = src[e];
    }
}

// ---------------------------------------------------------------------------
// Weight rounding to tf32 (rna), once per launch
// ---------------------------------------------------------------------------
__global__ void k_round(const float* __restrict__ W, float* __restrict__ out, int n) {
    int i = blockIdx.x * blockDim.x + threadIdx.x;
    if (i < n) out[i] = rtf32(W[i]);
}

// ---------------------------------------------------------------------------
// GIN aggregation (gather, atomic-free), output pre-rounded to tf32
// ---------------------------------------------------------------------------
template <int DIM4>
__global__ void k_aggr(const float* __restrict__ h, float* __restrict__ z,
                       const float* __restrict__ eps, int layer) {
    const int NPB = 128 / DIM4;
    int v = blockIdx.x * NPB + threadIdx.x / DIM4;
    if (v >= N_NODES) return;
    int t = threadIdx.x % DIM4;
    float ep = 1.0f + eps[layer];
    const float4* h4 = (const float4*)h;
    float4 a = h4[(size_t)v * DIM4 + t];
    float4 acc;
    acc.x = ep * a.x; acc.y = ep * a.y; acc.z = ep * a.z; acc.w = ep * a.w;
    int j = g_rowptr[v], s1 = g_rowptr[v + 1];
    for (; j + 4 <= s1; j += 4) {
        int i0 = g_col[j], i1 = g_col[j + 1], i2 = g_col[j + 2], i3 = g_col[j + 3];
        float4 b0 = h4[(size_t)i0 * DIM4 + t];
        float4 b1 = h4[(size_t)i1 * DIM4 + t];
        float4 b2 = h4[(size_t)i2 * DIM4 + t];
        float4 b3 = h4[(size_t)i3 * DIM4 + t];
        acc.x += (b0.x + b1.x) + (b2.x + b3.x);
        acc.y += (b0.y + b1.y) + (b2.y + b3.y);
        acc.z += (b0.z + b1.z) + (b2.z + b3.z);
        acc.w += (b0.w + b1.w) + (b2.w + b3.w);
    }
    for (; j < s1; ++j) {
        int s = g_col[j];
        float4 b = h4[(size_t)s * DIM4 + t];
        acc.x += b.x; acc.y += b.y; acc.z += b.z; acc.w += b.w;
    }
    // pre-round for the tf32 GEMM that consumes z
    acc.x = rtf32(acc.x); acc.y = rtf32(acc.y);
    acc.z = rtf32(acc.z); acc.w = rtf32(acc.w);
    ((float4*)z)[(size_t)v * DIM4 + t] = acc;
}

// ---------------------------------------------------------------------------
// Tensor-core GEMM (single-pass tf32; operands pre-rounded outside)
// C[n x 256] = epi(A[n x K] @ B[K x 256] + bias)
// 256 threads (8 warps 2x4), tile 128x128, BK=16, warp tile 64x32,
// cp.async double buffer, 2 CTAs/SM.
// ---------------------------------------------------------------------------
template <bool RESID, bool ROUND>
__global__ __launch_bounds__(256, 2)
void k_gemm(const float* __restrict__ A, const float* __restrict__ B,
            const float* __restrict__ bias, const float* __restrict__ R,
            float* __restrict__ C, int n, int K) {
    __shared__ float As[2][128][20];    // [m][k], pitch 20 -> conflict-free frags
    __shared__ float Bs[2][16][136];    // [k][n], pitch 136 -> conflict-free frags
    int row0 = blockIdx.y * 128;
    int col0 = blockIdx.x * 128;
    int tid  = threadIdx.x;
    int w    = tid >> 5;
    int lane = tid & 31;
    int qid  = lane >> 2;
    int tq   = lane & 3;
    int m0w  = (w >> 2) * 64;
    int n0w  = (w & 3) * 32;

    float acc[4][4][4];
#pragma unroll
    for (int i = 0; i < 4; i++)
#pragma unroll
        for (int jj = 0; jj < 4; jj++)
#pragma unroll
            for (int q = 0; q < 4; q++) acc[i][jj][q] = 0.f;

    const int NC = K >> 4;

    auto load_stage = [&](int kc, int s) {
        int k0 = kc * 16;
#pragma unroll
        for (int i = 0; i < 2; i++) {
            int seg = tid + i * 256;             // 512 A segments of 16B
            int row = seg >> 2;
            int c4  = (seg & 3) * 4;
            int gr  = row0 + row;
            const float* srcp = &A[(size_t)(gr < n ? gr : 0) * K + k0 + c4];
            cp16p(&As[s][row][c4], srcp, gr < n ? 16 : 0);
        }
#pragma unroll
        for (int i = 0; i < 2; i++) {
            int seg = tid + i * 256;             // 512 B segments of 16B
            int row = seg >> 5;
            int c4  = (seg & 31) * 4;
            cp16(&Bs[s][row][c4], &B[(size_t)(k0 + row) * 256 + col0 + c4]);
        }
        CP_COMMIT();
    };

    load_stage(0, 0);
    for (int kc = 0; kc < NC; kc++) {
        int s = kc & 1;
        if (kc + 1 < NC) {
            load_stage(kc + 1, s ^ 1);
            asm volatile("cp.async.wait_group 1;" ::: "memory");
        } else {
            asm volatile("cp.async.wait_group 0;" ::: "memory");
        }
        __syncthreads();

#pragma unroll
        for (int kk = 0; kk < 16; kk += 8) {
            uint32_t a[4][4], b[4][2];
#pragma unroll
            for (int mb = 0; mb < 4; mb++) {
                int r0 = m0w + mb * 16 + qid;
                a[mb][0] = __float_as_uint(As[s][r0][kk + tq]);
                a[mb][1] = __float_as_uint(As[s][r0 + 8][kk + tq]);
                a[mb][2] = __float_as_uint(As[s][r0][kk + tq + 4]);
                a[mb][3] = __float_as_uint(As[s][r0 + 8][kk + tq + 4]);
            }
#pragma unroll
            for (int nb = 0; nb < 4; nb++) {
                int c = n0w + nb * 8 + qid;
                b[nb][0] = __float_as_uint(Bs[s][kk + tq][c]);
                b[nb][1] = __float_as_uint(Bs[s][kk + tq + 4][c]);
            }
#pragma unroll
            for (int mb = 0; mb < 4; mb++)
#pragma unroll
                for (int nb = 0; nb < 4; nb++)
                    mma8(acc[mb][nb], a[mb], b[nb]);
        }
        __syncthreads();
    }

    // epilogue: bias + ReLU (+ residual) (+ tf32 pre-round of output)
#pragma unroll
    for (int mb = 0; mb < 4; mb++) {
        int r0g = row0 + m0w + mb * 16 + qid;
        int r1g = r0g + 8;
#pragma unroll
        for (int nb = 0; nb < 4; nb++) {
            int cg = col0 + n0w + nb * 8 + tq * 2;
            float bs0 = bias[cg], bs1 = bias[cg + 1];
            if (r0g < n) {
                float v0 = fmaxf(acc[mb][nb][0] + bs0, 0.f);
                float v1 = fmaxf(acc[mb][nb][1] + bs1, 0.f);
                if (RESID) {
                    v0 += R[(size_t)r0g * 256 + cg];
                    v1 += R[(size_t)r0g * 256 + cg + 1];
                }
                if (ROUND) { v0 = rtf32(v0); v1 = rtf32(v1); }
                C[(size_t)r0g * 256 + cg]     = v0;
                C[(size_t)r0g * 256 + cg + 1] = v1;
            }
            if (r1g < n) {
                float v2 = fmaxf(acc[mb][nb][2] + bs0, 0.f);
                float v3 = fmaxf(acc[mb][nb][3] + bs1, 0.f);
                if (RESID) {
                    v2 += R[(size_t)r1g * 256 + cg];
                    v3 += R[(size_t)r1g * 256 + cg + 1];
                }
                if (ROUND) { v2 = rtf32(v2); v3 = rtf32(v3); }
                C[(size_t)r1g * 256 + cg]     = v2;
                C[(size_t)r1g * 256 + cg + 1] = v3;
            }
        }
    }
}

// ---------------------------------------------------------------------------
// Pooling (sorted batch -> run-length accumulate)
// ---------------------------------------------------------------------------
__global__ void k_pool(const float* __restrict__ h, const int* __restrict__ batch) {
    __shared__ int sb[128];
    int i0 = blockIdx.x * 128;
    int d = threadIdx.x;
    int end = N_NODES - i0;
    if (end > 128) end = 128;
    if (d < 128 && d < end) sb[d] = batch[i0 + d];
    __syncthreads();
    int cur = sb[0];
    float acc = 0.f;
    for (int t = 0; t < end; t++) {
        int b = sb[t];
        if (b != cur) {
            atomicAdd(&g_pooled[cur * HIDDEN + d], acc);
            acc = 0.f;
            cur = b;
        }
        acc += h[(size_t)(i0 + t) * HIDDEN + d];
    }
    atomicAdd(&g_pooled[cur * HIDDEN + d], acc);
    if (d == 0) {
        int c = 0, cb = sb[0];
        for (int t = 0; t < end; t++) {
            if (sb[t] != cb) {
                atomicAdd(&g_cnt[cb], (float)c);
                c = 0;
                cb = sb[t];
            }
            c++;
        }
        atomicAdd(&g_cnt[cb], (float)c);
    }
}

// ---------------------------------------------------------------------------
// Head
// ---------------------------------------------------------------------------
__global__ void k_head(const float* __restrict__ g,
                       const float* __restrict__ hW1, const float* __restrict__ hb1,
                       const float* __restrict__ hW2, const float* __restrict__ hb2,
                       float* __restrict__ out) {
    __shared__ float feat[HIDDEN + GLOB_DIM];
    __shared__ float red[256];
    int gi = blockIdx.x;
    int t = threadIdx.x;
    float cnt = fmaxf(g_cnt[gi], 1.0f);
    feat[t] = g_pooled[gi * HIDDEN + t] / cnt;
    if (t < GLOB_DIM) feat[HIDDEN + t] = g[gi * GLOB_DIM + t];
    __syncthreads();
    float acc = hb1[t];
    for (int k = 0; k < HIDDEN + GLOB_DIM; k++)
        acc += feat[k] * hW1[k * HIDDEN + t];
    acc = fmaxf(acc, 0.f) * hW2[t];
    red[t] = acc;
    __syncthreads();
    for (int off = 128; off > 0; off >>= 1) {
        if (t < off) red[t] += red[t + off];
        __syncthreads();
    }
    if (t == 0) out[gi] = red[0] + hb2[0];
}

// ---------------------------------------------------------------------------
// kernel_launch
// ---------------------------------------------------------------------------
extern "C" void kernel_launch(void* const* d_in, const int* in_sizes, int n_in,
                              void* d_out, int out_size) {
    const float* x     = (const float*)d_in[0];
    const int*   ei    = (const int*)  d_in[1];
    const int*   batch = (const int*)  d_in[2];
    const float* g     = (const float*)d_in[3];
    const float* W1[NUM_LAYERS], *b1[NUM_LAYERS], *W2[NUM_LAYERS], *b2[NUM_LAYERS];
    for (int l = 0; l < NUM_LAYERS; l++) {
        W1[l] = (const float*)d_in[4 + 4 * l + 0];
        b1[l] = (const float*)d_in[4 + 4 * l + 1];
        W2[l] = (const float*)d_in[4 + 4 * l + 2];
        b2[l] = (const float*)d_in[4 + 4 * l + 3];
    }
    const float* eps = (const float*)d_in[20];
    const float* hW1 = (const float*)d_in[21];
    const float* hb1 = (const float*)d_in[22];
    const float* hW2 = (const float*)d_in[23];
    const float* hb2 = (const float*)d_in[24];
    float* out = (float*)d_out;

    const int* src = ei;
    const int* dst = ei + N_EDGES;

    float *hA, *hB, *z, *t, *wr;
    cudaGetSymbolAddress((void**)&hA, g_hA);
    cudaGetSymbolAddress((void**)&hB, g_hB);
    cudaGetSymbolAddress((void**)&z,  g_z);
    cudaGetSymbolAddress((void**)&t,  g_t);
    cudaGetSymbolAddress((void**)&wr, g_Wr);

    // CSR build
    k_zero <<<(N_NODES + 255) / 256, 256>>>();
    k_count<<<(N_EDGES + 255) / 256, 256>>>(dst);
    k_scan <<<1, 512>>>();
    k_fill <<<(N_EDGES + 255) / 256, 256>>>(src, dst);

    // Pre-round weights to tf32 (rna)
    for (int l = 0; l < NUM_LAYERS; l++) {
        int K1 = (l == 0) ? NODE_DIM : HIDDEN;
        float* wr1 = wr + (size_t)(2 * l)     * HIDDEN * HIDDEN;
        float* wr2 = wr + (size_t)(2 * l + 1) * HIDDEN * HIDDEN;
        k_round<<<(K1 * 256 + 255) / 256, 256>>>(W1[l], wr1, K1 * 256);
        k_round<<<(256 * 256 + 255) / 256, 256>>>(W2[l], wr2, 256 * 256);
    }

    dim3 ggrid(2, (N_NODES + 127) / 128);

    const float* h_in = x;
    float* h_out = hA;
    for (int l = 0; l < NUM_LAYERS; l++) {
        int din = (l == 0) ? NODE_DIM : HIDDEN;
        float* wr1 = wr + (size_t)(2 * l)     * HIDDEN * HIDDEN;
        float* wr2 = wr + (size_t)(2 * l + 1) * HIDDEN * HIDDEN;
        if (din == NODE_DIM)
            k_aggr<NODE_DIM / 4><<<(N_NODES + 3) / 4, 128>>>(h_in, z, eps, l);
        else
            k_aggr<HIDDEN / 4><<<(N_NODES + 1) / 2, 128>>>(h_in, z, eps, l);
        // t = relu(z @ W1 + b1), output pre-rounded (feeds next GEMM)
        k_gemm<false, true><<<ggrid, 256>>>(z, wr1, b1[l], nullptr, t, N_NODES, din);
        // h_out = relu(t @ W2 + b2) [+ h_in], fp32 output
        if (l == 0)
            k_gemm<false, false><<<ggrid, 256>>>(t, wr2, b2[l], nullptr, h_out, N_NODES, HIDDEN);
        else
            k_gemm<true,  false><<<ggrid, 256>>>(t, wr2, b2[l], h_in, h_out, N_NODES, HIDDEN);
        h_in = h_out;
        h_out = (h_out == hA) ? hB : hA;
    }

    k_pool<<<(N_NODES + 127) / 128, 256>>>(h_in, batch);
    k_head<<<N_GRAPHS, 256>>>(g, hW1, hb1, hW2, hb2, out);
}

// round 6
// speedup vs baseline: 2.1247x; 1.0480x over previous
#include <cuda_runtime.h>
#include <cstdint>
#include <cstddef>

// Problem constants
#define N_NODES   20000
#define N_EDGES   320000
#define N_GRAPHS  64
#define NODE_DIM  128
#define GLOB_DIM  16
#define HIDDEN    256
#define NUM_LAYERS 4

// ---------------------------------------------------------------------------
// Scratch (static __device__ allocations)
// ---------------------------------------------------------------------------
__device__ float g_hA[N_NODES * HIDDEN];
__device__ float g_hB[N_NODES * HIDDEN];
__device__ float g_z [N_NODES * HIDDEN];
__device__ float g_t [N_NODES * HIDDEN];
__device__ float g_Wr[NUM_LAYERS * 2][HIDDEN * HIDDEN];  // tf32-rounded weights

__device__ int   g_deg   [N_NODES];
__device__ int   g_rowptr[N_NODES + 1];
__device__ int   g_cursor[N_NODES];
__device__ int   g_col   [N_EDGES];

__device__ float g_pooled[N_GRAPHS * HIDDEN];
__device__ float g_cnt   [N_GRAPHS];

// ---------------------------------------------------------------------------
// Helpers
// ---------------------------------------------------------------------------
__device__ __forceinline__ float rtf32(float x) {
    uint32_t r;
    asm("cvt.rna.tf32.f32 %0, %1;" : "=r"(r) : "f"(x));
    return __uint_as_float(r);
}

__device__ __forceinline__ void mma8(float* c, const uint32_t* a, const uint32_t* b) {
    asm volatile(
        "mma.sync.aligned.m16n8k8.row.col.f32.tf32.tf32.f32 "
        "{%0,%1,%2,%3}, {%4,%5,%6,%7}, {%8,%9}, {%0,%1,%2,%3};"
        : "+f"(c[0]), "+f"(c[1]), "+f"(c[2]), "+f"(c[3])
        : "r"(a[0]), "r"(a[1]), "r"(a[2]), "r"(a[3]), "r"(b[0]), "r"(b[1]));
}

__device__ __forceinline__ void cp16p(void* dst, const void* src, int srcbytes) {
    uint32_t d = (uint32_t)__cvta_generic_to_shared(dst);
    asm volatile("cp.async.cg.shared.global [%0], [%1], 16, %2;"
                 :: "r"(d), "l"(src), "r"(srcbytes));
}
__device__ __forceinline__ void cp16(void* dst, const void* src) {
    uint32_t d = (uint32_t)__cvta_generic_to_shared(dst);
    asm volatile("cp.async.cg.shared.global [%0], [%1], 16;"
                 :: "r"(d), "l"(src));
}
#define CP_COMMIT() asm volatile("cp.async.commit_group;" ::: "memory")

// ---------------------------------------------------------------------------
// CSR build
// ---------------------------------------------------------------------------
__global__ void k_zero() {
    int i = blockIdx.x * blockDim.x + threadIdx.x;
    if (i < N_NODES) g_deg[i] = 0;
    if (i < N_GRAPHS * HIDDEN) g_pooled[i] = 0.f;
    if (i < N_GRAPHS) g_cnt[i] = 0.f;
}

__global__ void k_count(const int* __restrict__ dst) {
    int e = (blockIdx.x * blockDim.x + threadIdx.x) * 4;
#pragma unroll
    for (int j = 0; j < 4; j++)
        if (e + j < N_EDGES) atomicAdd(&g_deg[dst[e + j]], 1);
}

__global__ void k_scan() {
    const int T = 512;
    const int CH = (N_NODES + T - 1) / T;
    __shared__ int part[T];
    int t = threadIdx.x;
    int base = t * CH;
    int s = 0;
    for (int j = 0; j < CH; j++) {
        int i = base + j;
        if (i < N_NODES) s += g_deg[i];
    }
    part[t] = s;
    __syncthreads();
    for (int off = 1; off < T; off <<= 1) {
        int v = (t >= off) ? part[t - off] : 0;
        __syncthreads();
        part[t] += v;
        __syncthreads();
    }
    int run = (t > 0) ? part[t - 1] : 0;
    for (int j = 0; j < CH; j++) {
        int i = base + j;
        if (i < N_NODES) {
            g_rowptr[i] = run;
            g_cursor[i] = run;
            run += g_deg[i];
        }
    }
    if (t == T - 1) g_rowptr[N_NODES] = run;
}

__global__ void k_fill(const int* __restrict__ src, const int* __restrict__ dst) {
    int e = (blockIdx.x * blockDim.x + threadIdx.x) * 4;
#pragma unroll
    for (int j = 0; j < 4; j++) {
        if (e + j < N_EDGES) {
            int d = dst[e + j];
            int p = atomicAdd(&g_cursor[d], 1);
            g_col[p] = src[e + j];
        }
    }
}

// ---------------------------------------------------------------------------
// Weight rounding to tf32 (rna), all 8 matrices in one kernel
// ---------------------------------------------------------------------------
struct P8 { const float* p[8]; int n[8]; };

__global__ void k_round_all(P8 ps, float* __restrict__ out) {
    int i = blockIdx.x * blockDim.x + threadIdx.x;
    int slot = i >> 16;
    int off  = i & 65535;
    if (slot < 8 && off < ps.n[slot])
        out[(size_t)slot * 65536 + off] = rtf32(ps.p[slot][off]);
}

// ---------------------------------------------------------------------------
// GIN aggregation (gather, atomic-free), output pre-rounded to tf32
// ---------------------------------------------------------------------------
template <int DIM4>
__global__ void k_aggr(const float* __restrict__ h, float* __restrict__ z,
                       const float* __restrict__ eps, int layer) {
    const int NPB = 128 / DIM4;
    int v = blockIdx.x * NPB + threadIdx.x / DIM4;
    if (v >= N_NODES) return;
    int t = threadIdx.x % DIM4;
    float ep = 1.0f + eps[layer];
    const float4* h4 = (const float4*)h;
    float4 a = h4[(size_t)v * DIM4 + t];
    float4 acc;
    acc.x = ep * a.x; acc.y = ep * a.y; acc.z = ep * a.z; acc.w = ep * a.w;
    int j = g_rowptr[v], s1 = g_rowptr[v + 1];
    for (; j + 4 <= s1; j += 4) {
        int i0 = g_col[j], i1 = g_col[j + 1], i2 = g_col[j + 2], i3 = g_col[j + 3];
        float4 b0 = h4[(size_t)i0 * DIM4 + t];
        float4 b1 = h4[(size_t)i1 * DIM4 + t];
        float4 b2 = h4[(size_t)i2 * DIM4 + t];
        float4 b3 = h4[(size_t)i3 * DIM4 + t];
        acc.x += (b0.x + b1.x) + (b2.x + b3.x);
        acc.y += (b0.y + b1.y) + (b2.y + b3.y);
        acc.z += (b0.z + b1.z) + (b2.z + b3.z);
        acc.w += (b0.w + b1.w) + (b2.w + b3.w);
    }
    for (; j < s1; ++j) {
        int s = g_col[j];
        float4 b = h4[(size_t)s * DIM4 + t];
        acc.x += b.x; acc.y += b.y; acc.z += b.z; acc.w += b.w;
    }
    acc.x = rtf32(acc.x); acc.y = rtf32(acc.y);
    acc.z = rtf32(acc.z); acc.w = rtf32(acc.w);
    ((float4*)z)[(size_t)v * DIM4 + t] = acc;
}

// ---------------------------------------------------------------------------
// Tensor-core GEMM, single-pass tf32 (operands pre-rounded).
// C[n x 256] = epi(A[n x K] @ B[K x 256] + bias)
// 128 threads (4 warps), CTA tile 128x128, warp tile 64x64, BK=16,
// 3-stage cp.async ring (dynamic smem), 2 CTAs/SM.
// ---------------------------------------------------------------------------
static constexpr int AS_FLOATS = 128 * 20;   // per stage
static constexpr int BS_FLOATS = 16 * 136;   // per stage
static constexpr int GEMM_SMEM_BYTES = (3 * AS_FLOATS + 3 * BS_FLOATS) * 4;

template <bool RESID, bool ROUND>
__global__ __launch_bounds__(128, 2)
void k_gemm(const float* __restrict__ A, const float* __restrict__ B,
            const float* __restrict__ bias, const float* __restrict__ R,
            float* __restrict__ C, int n, int K) {
    extern __shared__ float smem[];
    float (*As)[128][20]  = (float(*)[128][20])smem;
    float (*Bs)[16][136]  = (float(*)[16][136])(smem + 3 * AS_FLOATS);

    int row0 = blockIdx.y * 128;
    int col0 = blockIdx.x * 128;
    int tid  = threadIdx.x;
    int w    = tid >> 5;
    int lane = tid & 31;
    int qid  = lane >> 2;
    int tq   = lane & 3;
    int m0w  = (w >> 1) * 64;
    int n0w  = (w & 1) * 64;

    float acc[4][8][4];
#pragma unroll
    for (int i = 0; i < 4; i++)
#pragma unroll
        for (int jj = 0; jj < 8; jj++)
#pragma unroll
            for (int q = 0; q < 4; q++) acc[i][jj][q] = 0.f;

    const int NC = K >> 4;

    auto load_stage = [&](int kc, int s) {
        int k0 = kc * 16;
#pragma unroll
        for (int i = 0; i < 4; i++) {
            int seg = tid + i * 128;            // 512 A segments of 16B
            int row = seg >> 2;
            int c4  = (seg & 3) * 4;
            int gr  = row0 + row;
            const float* srcp = &A[(size_t)(gr < n ? gr : 0) * K + k0 + c4];
            cp16p(&As[s][row][c4], srcp, gr < n ? 16 : 0);
        }
#pragma unroll
        for (int i = 0; i < 4; i++) {
            int seg = tid + i * 128;            // 512 B segments of 16B
            int row = seg >> 5;
            int c4  = (seg & 31) * 4;
            cp16(&Bs[s][row][c4], &B[(size_t)(k0 + row) * 256 + col0 + c4]);
        }
        CP_COMMIT();
    };

    load_stage(0, 0);
    if (NC > 1) load_stage(1, 1);

    for (int kc = 0; kc < NC; kc++) {
        if (kc + 1 < NC) asm volatile("cp.async.wait_group 1;" ::: "memory");
        else             asm volatile("cp.async.wait_group 0;" ::: "memory");
        __syncthreads();
        if (kc + 2 < NC) load_stage(kc + 2, (kc + 2) % 3);

        int s = kc % 3;
#pragma unroll
        for (int kk = 0; kk < 16; kk += 8) {
            uint32_t a[4][4], b[8][2];
#pragma unroll
            for (int mb = 0; mb < 4; mb++) {
                int r0 = m0w + mb * 16 + qid;
                a[mb][0] = __float_as_uint(As[s][r0][kk + tq]);
                a[mb][1] = __float_as_uint(As[s][r0 + 8][kk + tq]);
                a[mb][2] = __float_as_uint(As[s][r0][kk + tq + 4]);
                a[mb][3] = __float_as_uint(As[s][r0 + 8][kk + tq + 4]);
            }
#pragma unroll
            for (int nb = 0; nb < 8; nb++) {
                int c = n0w + nb * 8 + qid;
                b[nb][0] = __float_as_uint(Bs[s][kk + tq][c]);
                b[nb][1] = __float_as_uint(Bs[s][kk + tq + 4][c]);
            }
#pragma unroll
            for (int mb = 0; mb < 4; mb++)
#pragma unroll
                for (int nb = 0; nb < 8; nb++)
                    mma8(acc[mb][nb], a[mb], b[nb]);
        }
        __syncthreads();
    }

    // epilogue: bias + ReLU (+ residual) (+ tf32 pre-round of output)
#pragma unroll
    for (int mb = 0; mb < 4; mb++) {
        int r0g = row0 + m0w + mb * 16 + qid;
        int r1g = r0g + 8;
#pragma unroll
        for (int nb = 0; nb < 8; nb++) {
            int cg = col0 + n0w + nb * 8 + tq * 2;
            float bs0 = bias[cg], bs1 = bias[cg + 1];
            if (r0g < n) {
                float v0 = fmaxf(acc[mb][nb][0] + bs0, 0.f);
                float v1 = fmaxf(acc[mb][nb][1] + bs1, 0.f);
                if (RESID) {
                    v0 += R[(size_t)r0g * 256 + cg];
                    v1 += R[(size_t)r0g * 256 + cg + 1];
                }
                if (ROUND) { v0 = rtf32(v0); v1 = rtf32(v1); }
                C[(size_t)r0g * 256 + cg]     = v0;
                C[(size_t)r0g * 256 + cg + 1] = v1;
            }
            if (r1g < n) {
                float v2 = fmaxf(acc[mb][nb][2] + bs0, 0.f);
                float v3 = fmaxf(acc[mb][nb][3] + bs1, 0.f);
                if (RESID) {
                    v2 += R[(size_t)r1g * 256 + cg];
                    v3 += R[(size_t)r1g * 256 + cg + 1];
                }
                if (ROUND) { v2 = rtf32(v2); v3 = rtf32(v3); }
                C[(size_t)r1g * 256 + cg]     = v2;
                C[(size_t)r1g * 256 + cg + 1] = v3;
            }
        }
    }
}

// ---------------------------------------------------------------------------
// Pooling (sorted batch -> run-length accumulate)
// ---------------------------------------------------------------------------
__global__ void k_pool(const float* __restrict__ h, const int* __restrict__ batch) {
    __shared__ int sb[128];
    int i0 = blockIdx.x * 128;
    int d = threadIdx.x;
    int end = N_NODES - i0;
    if (end > 128) end = 128;
    if (d < 128 && d < end) sb[d] = batch[i0 + d];
    __syncthreads();
    int cur = sb[0];
    float acc = 0.f;
    for (int t = 0; t < end; t++) {
        int b = sb[t];
        if (b != cur) {
            atomicAdd(&g_pooled[cur * HIDDEN + d], acc);
            acc = 0.f;
            cur = b;
        }
        acc += h[(size_t)(i0 + t) * HIDDEN + d];
    }
    atomicAdd(&g_pooled[cur * HIDDEN + d], acc);
    if (d == 0) {
        int c = 0, cb = sb[0];
        for (int t = 0; t < end; t++) {
            if (sb[t] != cb) {
                atomicAdd(&g_cnt[cb], (float)c);
                c = 0;
                cb = sb[t];
            }
            c++;
        }
        atomicAdd(&g_cnt[cb], (float)c);
    }
}

// ---------------------------------------------------------------------------
// Head
// ---------------------------------------------------------------------------
__global__ void k_head(const float* __restrict__ g,
                       const float* __restrict__ hW1, const float* __restrict__ hb1,
                       const float* __restrict__ hW2, const float* __restrict__ hb2,
                       float* __restrict__ out) {
    __shared__ float feat[HIDDEN + GLOB_DIM];
    __shared__ float red[256];
    int gi = blockIdx.x;
    int t = threadIdx.x;
    float cnt = fmaxf(g_cnt[gi], 1.0f);
    feat[t] = g_pooled[gi * HIDDEN + t] / cnt;
    if (t < GLOB_DIM) feat[HIDDEN + t] = g[gi * GLOB_DIM + t];
    __syncthreads();
    float acc = hb1[t];
    for (int k = 0; k < HIDDEN + GLOB_DIM; k++)
        acc += feat[k] * hW1[k * HIDDEN + t];
    acc = fmaxf(acc, 0.f) * hW2[t];
    red[t] = acc;
    __syncthreads();
    for (int off = 128; off > 0; off >>= 1) {
        if (t < off) red[t] += red[t + off];
        __syncthreads();
    }
    if (t == 0) out[gi] = red[0] + hb2[0];
}

// ---------------------------------------------------------------------------
// kernel_launch
// ---------------------------------------------------------------------------
extern "C" void kernel_launch(void* const* d_in, const int* in_sizes, int n_in,
                              void* d_out, int out_size) {
    const float* x     = (const float*)d_in[0];
    const int*   ei    = (const int*)  d_in[1];
    const int*   batch = (const int*)  d_in[2];
    const float* g     = (const float*)d_in[3];
    const float* W1[NUM_LAYERS], *b1[NUM_LAYERS], *W2[NUM_LAYERS], *b2[NUM_LAYERS];
    for (int l = 0; l < NUM_LAYERS; l++) {
        W1[l] = (const float*)d_in[4 + 4 * l + 0];
        b1[l] = (const float*)d_in[4 + 4 * l + 1];
        W2[l] = (const float*)d_in[4 + 4 * l + 2];
        b2[l] = (const float*)d_in[4 + 4 * l + 3];
    }
    const float* eps = (const float*)d_in[20];
    const float* hW1 = (const float*)d_in[21];
    const float* hb1 = (const float*)d_in[22];
    const float* hW2 = (const float*)d_in[23];
    const float* hb2 = (const float*)d_in[24];
    float* out = (float*)d_out;

    const int* src = ei;
    const int* dst = ei + N_EDGES;

    float *hA, *hB, *z, *t, *wr;
    cudaGetSymbolAddress((void**)&hA, g_hA);
    cudaGetSymbolAddress((void**)&hB, g_hB);
    cudaGetSymbolAddress((void**)&z,  g_z);
    cudaGetSymbolAddress((void**)&t,  g_t);
    cudaGetSymbolAddress((void**)&wr, g_Wr);

    cudaFuncSetAttribute(k_gemm<false, true >, cudaFuncAttributeMaxDynamicSharedMemorySize, GEMM_SMEM_BYTES);
    cudaFuncSetAttribute(k_gemm<false, false>, cudaFuncAttributeMaxDynamicSharedMemorySize, GEMM_SMEM_BYTES);
    cudaFuncSetAttribute(k_gemm<true,  false>, cudaFuncAttributeMaxDynamicSharedMemorySize, GEMM_SMEM_BYTES);

    // CSR build
    k_zero <<<(N_NODES + 255) / 256, 256>>>();
    k_count<<<(N_EDGES / 4 + 255) / 256, 256>>>(dst);
    k_scan <<<1, 512>>>();
    k_fill <<<(N_EDGES / 4 + 255) / 256, 256>>>(src, dst);

    // Pre-round all weights to tf32 in one kernel
    {
        P8 ps;
        for (int l = 0; l < NUM_LAYERS; l++) {
            ps.p[2 * l]     = W1[l];
            ps.n[2 * l]     = ((l == 0) ? NODE_DIM : HIDDEN) * HIDDEN;
            ps.p[2 * l + 1] = W2[l];
            ps.n[2 * l + 1] = HIDDEN * HIDDEN;
        }
        k_round_all<<<(8 * 65536) / 256, 256>>>(ps, wr);
    }

    dim3 ggrid(2, (N_NODES + 127) / 128);

    const float* h_in = x;
    float* h_out = hA;
    for (int l = 0; l < NUM_LAYERS; l++) {
        int din = (l == 0) ? NODE_DIM : HIDDEN;
        float* wr1 = wr + (size_t)(2 * l)     * HIDDEN * HIDDEN;
        float* wr2 = wr + (size_t)(2 * l + 1) * HIDDEN * HIDDEN;
        if (din == NODE_DIM)
            k_aggr<NODE_DIM / 4><<<(N_NODES + 3) / 4, 128>>>(h_in, z, eps, l);
        else
            k_aggr<HIDDEN / 4><<<(N_NODES + 1) / 2, 128>>>(h_in, z, eps, l);
        k_gemm<false, true><<<ggrid, 128, GEMM_SMEM_BYTES>>>(z, wr1, b1[l], nullptr, t, N_NODES, din);
        if (l == 0)
            k_gemm<false, false><<<ggrid, 128, GEMM_SMEM_BYTES>>>(t, wr2, b2[l], nullptr, h_out, N_NODES, HIDDEN);
        else
            k_gemm<true,  false><<<ggrid, 128, GEMM_SMEM_BYTES>>>(t, wr2, b2[l], h_in, h_out, N_NODES, HIDDEN);
        h_in = h_out;
        h_out = (h_out == hA) ? hB : hA;
    }

    k_pool<<<(N_NODES + 127) / 128, 256>>>(h_in, batch);
    k_head<<<N_GRAPHS, 256>>>(g, hW1, hb1, hW2, hb2, out);
}